// round 1
// baseline (speedup 1.0000x reference)
#include <cuda_runtime.h>

#define D 64
#define MAXN 50000
#define MAXE 800000
#define MAXG 512
#define MAXV 128

// ---------------- scratch (device globals; no allocation) ----------------
__device__ __align__(128) float g_embW[MAXV * D];   // (emb @ W_gcn), 32KB hot table
__device__ __align__(128) float g_h1[MAXN * D];
__device__ __align__(128) float g_deg[MAXN];
__device__ __align__(128) float g_nb[MAXN * D];     // SAGE neighbor sum
__device__ __align__(128) float g_h2[MAXN * D];
__device__ __align__(128) float g_agg[MAXN * D];    // GIN neighbor sum
__device__ __align__(128) float g_h3[MAXN * D];
__device__ __align__(128) float g_ps1[MAXG * D];    // pooled sums
__device__ __align__(128) float g_ps2[MAXG * D];
__device__ __align__(128) float g_ps3[MAXG * D];
__device__ __align__(128) float g_cnt[MAXG];

// vectorized no-return global reduction (sm_90+)
__device__ __forceinline__ void red_add_v4(float* addr, float4 v) {
    asm volatile("red.global.add.v4.f32 [%0], {%1,%2,%3,%4};"
                 :: "l"(addr), "f"(v.x), "f"(v.y), "f"(v.z), "f"(v.w)
                 : "memory");
}

// ---------------- zero scratch ----------------
__global__ void k_zero() {
    int i = blockIdx.x * blockDim.x + threadIdx.x;
    int stride = gridDim.x * blockDim.x;
    for (int j = i; j < MAXN * D; j += stride) { g_h1[j] = 0.f; g_nb[j] = 0.f; g_agg[j] = 0.f; }
    for (int j = i; j < MAXN; j += stride) g_deg[j] = 0.f;
    for (int j = i; j < MAXG * D; j += stride) { g_ps1[j] = 0.f; g_ps2[j] = 0.f; g_ps3[j] = 0.f; }
    for (int j = i; j < MAXG; j += stride) g_cnt[j] = 0.f;
}

// ---------------- embW = emb @ W_gcn  (V x D @ D x D, tiny) ----------------
__global__ void k_embw(const float* __restrict__ emb, const float* __restrict__ W, int Vn) {
    int idx = blockIdx.x * blockDim.x + threadIdx.x;
    if (idx >= Vn * D) return;
    int v = idx >> 6, j = idx & 63;
    float s = 0.f;
#pragma unroll
    for (int k = 0; k < D; k++) s += emb[v * D + k] * W[k * D + j];
    g_embW[idx] = s;
}

// ---------------- GCN edge pass: h1[dst] += embW[x[src]]; deg[dst] += 1 ----
// 16 threads per edge, each handles one float4.
__global__ void k_edge_gcn(const int* __restrict__ ei, const int* __restrict__ x, int E_) {
    int gid = blockIdx.x * blockDim.x + threadIdx.x;
    if (gid >= E_ * 16) return;
    int e = gid >> 4, q = gid & 15;
    int src = ei[e];
    int dst = ei[E_ + e];
    int row = x[src];
    float4 v = reinterpret_cast<const float4*>(g_embW + row * D)[q];
    red_add_v4(g_h1 + dst * D + q * 4, v);
    if (q == 0) atomicAdd(&g_deg[dst], 1.0f);
}

// ---------------- generic edge scatter: out[dst] += hin[src] ---------------
// mode 0: g_h1 -> g_nb ; mode 1: g_h2 -> g_agg
__global__ void k_edge_scatter(const int* __restrict__ ei, int E_, int mode) {
    int gid = blockIdx.x * blockDim.x + threadIdx.x;
    if (gid >= E_ * 16) return;
    int e = gid >> 4, q = gid & 15;
    int src = ei[e];
    int dst = ei[E_ + e];
    const float* hin = (mode == 0) ? g_h1 : g_h2;
    float* outp = (mode == 0) ? g_nb : g_agg;
    float4 v = reinterpret_cast<const float4*>(hin + src * D)[q];
    red_add_v4(outp + dst * D + q * 4, v);
}

// ---------------- relu in place on h1 ----------------
__global__ void k_relu1(int total) {
    int i = blockIdx.x * blockDim.x + threadIdx.x;
    if (i < total) g_h1[i] = fmaxf(g_h1[i], 0.f);
}

// ---------------- SAGE: h2 = relu((nb/deg) @ Wl + h1 @ Wr) ----------------
// 1 warp per node; thread j computes output cols j and j+32; input row broadcast via shfl.
__global__ void k_sage(const float* __restrict__ Wl, const float* __restrict__ Wr, int n_nodes) {
    __shared__ float sWl[D * D];
    __shared__ float sWr[D * D];
    for (int i = threadIdx.x; i < D * D; i += blockDim.x) { sWl[i] = Wl[i]; sWr[i] = Wr[i]; }
    __syncthreads();
    int warp = threadIdx.x >> 5, lane = threadIdx.x & 31;
    int n = blockIdx.x * 8 + warp;
    if (n >= n_nodes) return;
    float invd = 1.0f / fmaxf(g_deg[n], 1.0f);
    float nb0 = g_nb[n * D + lane] * invd;
    float nb1 = g_nb[n * D + lane + 32] * invd;
    float h0 = g_h1[n * D + lane];
    float h1v = g_h1[n * D + lane + 32];
    float acc0 = 0.f, acc1 = 0.f;
#pragma unroll
    for (int k = 0; k < 32; k++) {
        float m = __shfl_sync(0xffffffffu, nb0, k);
        float h = __shfl_sync(0xffffffffu, h0, k);
        acc0 += m * sWl[k * D + lane] + h * sWr[k * D + lane];
        acc1 += m * sWl[k * D + lane + 32] + h * sWr[k * D + lane + 32];
    }
#pragma unroll
    for (int k = 0; k < 32; k++) {
        float m = __shfl_sync(0xffffffffu, nb1, k);
        float h = __shfl_sync(0xffffffffu, h1v, k);
        acc0 += m * sWl[(k + 32) * D + lane] + h * sWr[(k + 32) * D + lane];
        acc1 += m * sWl[(k + 32) * D + lane + 32] + h * sWr[(k + 32) * D + lane + 32];
    }
    g_h2[n * D + lane] = fmaxf(acc0, 0.f);
    g_h2[n * D + lane + 32] = fmaxf(acc1, 0.f);
}

// ---------------- GIN: h3 = relu(relu((h2+agg)@W1+b1)@W2+b2) ----------------
__global__ void k_gin(const float* __restrict__ W1, const float* __restrict__ b1,
                      const float* __restrict__ W2, const float* __restrict__ b2, int n_nodes) {
    __shared__ float sW1[D * D];
    __shared__ float sW2[D * D];
    __shared__ float sb1[D];
    __shared__ float sb2[D];
    for (int i = threadIdx.x; i < D * D; i += blockDim.x) { sW1[i] = W1[i]; sW2[i] = W2[i]; }
    for (int i = threadIdx.x; i < D; i += blockDim.x) { sb1[i] = b1[i]; sb2[i] = b2[i]; }
    __syncthreads();
    int warp = threadIdx.x >> 5, lane = threadIdx.x & 31;
    int n = blockIdx.x * 8 + warp;
    if (n >= n_nodes) return;
    float z0 = g_h2[n * D + lane] + g_agg[n * D + lane];
    float z1 = g_h2[n * D + lane + 32] + g_agg[n * D + lane + 32];
    float t0 = sb1[lane], t1 = sb1[lane + 32];
#pragma unroll
    for (int k = 0; k < 32; k++) {
        float z = __shfl_sync(0xffffffffu, z0, k);
        t0 += z * sW1[k * D + lane];
        t1 += z * sW1[k * D + lane + 32];
    }
#pragma unroll
    for (int k = 0; k < 32; k++) {
        float z = __shfl_sync(0xffffffffu, z1, k);
        t0 += z * sW1[(k + 32) * D + lane];
        t1 += z * sW1[(k + 32) * D + lane + 32];
    }
    t0 = fmaxf(t0, 0.f);
    t1 = fmaxf(t1, 0.f);
    float o0 = sb2[lane], o1 = sb2[lane + 32];
#pragma unroll
    for (int k = 0; k < 32; k++) {
        float t = __shfl_sync(0xffffffffu, t0, k);
        o0 += t * sW2[k * D + lane];
        o1 += t * sW2[k * D + lane + 32];
    }
#pragma unroll
    for (int k = 0; k < 32; k++) {
        float t = __shfl_sync(0xffffffffu, t1, k);
        o0 += t * sW2[(k + 32) * D + lane];
        o1 += t * sW2[(k + 32) * D + lane + 32];
    }
    g_h3[n * D + lane] = fmaxf(o0, 0.f);
    g_h3[n * D + lane + 32] = fmaxf(o1, 0.f);
}

// ---------------- pooling: per-graph sums; batch is SORTED -> run flushing ----
#define POOL_CHUNK 64
__global__ void k_pool(const int* __restrict__ batch, int n_nodes) {
    int j = threadIdx.x;  // 0..63 (column)
    int n0 = blockIdx.x * POOL_CHUNK;
    int nend = n0 + POOL_CHUNK;
    if (nend > n_nodes) nend = n_nodes;
    int g = -1;
    float s1 = 0.f, s2 = 0.f, s3 = 0.f, c = 0.f;
    for (int n = n0; n < nend; n++) {
        int bg = batch[n];
        if (bg != g) {
            if (g >= 0) {
                atomicAdd(&g_ps1[g * D + j], s1);
                atomicAdd(&g_ps2[g * D + j], s2);
                atomicAdd(&g_ps3[g * D + j], s3);
                if (j == 0) atomicAdd(&g_cnt[g], c);
            }
            g = bg; s1 = s2 = s3 = 0.f; c = 0.f;
        }
        s1 += g_h1[n * D + j];
        s2 += g_h2[n * D + j];
        s3 += g_h3[n * D + j];
        c += 1.0f;
    }
    if (g >= 0) {
        atomicAdd(&g_ps1[g * D + j], s1);
        atomicAdd(&g_ps2[g * D + j], s2);
        atomicAdd(&g_ps3[g * D + j], s3);
        if (j == 0) atomicAdd(&g_cnt[g], c);
    }
}

// ---------------- final: out = relu(mean1@Wp1 + mean2@Wp2 + mean3@Wp3) ------
__global__ void k_final(const float* __restrict__ Wp1, const float* __restrict__ Wp2,
                        const float* __restrict__ Wp3, float* __restrict__ out, int Gn) {
    __shared__ float s1[D * D];
    __shared__ float s2[D * D];
    __shared__ float s3[D * D];
    for (int i = threadIdx.x; i < D * D; i += blockDim.x) { s1[i] = Wp1[i]; s2[i] = Wp2[i]; s3[i] = Wp3[i]; }
    __syncthreads();
    int warp = threadIdx.x >> 5, lane = threadIdx.x & 31;
    int g = blockIdx.x * 8 + warp;
    if (g >= Gn) return;
    float ic = 1.0f / fmaxf(g_cnt[g], 1.0f);
    float a0 = g_ps1[g * D + lane] * ic, a1 = g_ps1[g * D + lane + 32] * ic;
    float b0 = g_ps2[g * D + lane] * ic, b1 = g_ps2[g * D + lane + 32] * ic;
    float c0 = g_ps3[g * D + lane] * ic, c1 = g_ps3[g * D + lane + 32] * ic;
    float acc0 = 0.f, acc1 = 0.f;
#pragma unroll
    for (int k = 0; k < 32; k++) {
        float va = __shfl_sync(0xffffffffu, a0, k);
        float vb = __shfl_sync(0xffffffffu, b0, k);
        float vc = __shfl_sync(0xffffffffu, c0, k);
        acc0 += va * s1[k * D + lane] + vb * s2[k * D + lane] + vc * s3[k * D + lane];
        acc1 += va * s1[k * D + lane + 32] + vb * s2[k * D + lane + 32] + vc * s3[k * D + lane + 32];
    }
#pragma unroll
    for (int k = 0; k < 32; k++) {
        float va = __shfl_sync(0xffffffffu, a1, k);
        float vb = __shfl_sync(0xffffffffu, b1, k);
        float vc = __shfl_sync(0xffffffffu, c1, k);
        acc0 += va * s1[(k + 32) * D + lane] + vb * s2[(k + 32) * D + lane] + vc * s3[(k + 32) * D + lane];
        acc1 += va * s1[(k + 32) * D + lane + 32] + vb * s2[(k + 32) * D + lane + 32] + vc * s3[(k + 32) * D + lane + 32];
    }
    out[g * D + lane] = fmaxf(acc0, 0.f);
    out[g * D + lane + 32] = fmaxf(acc1, 0.f);
}

// ---------------- launch ----------------
extern "C" void kernel_launch(void* const* d_in, const int* in_sizes, int n_in,
                              void* d_out, int out_size) {
    const int* x      = (const int*)d_in[0];
    const int* ei     = (const int*)d_in[1];
    const int* batch  = (const int*)d_in[2];
    const float* emb  = (const float*)d_in[3];
    const float* Wgcn = (const float*)d_in[4];
    const float* Wsl  = (const float*)d_in[5];
    const float* Wsr  = (const float*)d_in[6];
    const float* Wg1  = (const float*)d_in[7];
    const float* bg1  = (const float*)d_in[8];
    const float* Wg2  = (const float*)d_in[9];
    const float* bg2  = (const float*)d_in[10];
    const float* Wp1  = (const float*)d_in[11];
    const float* Wp2  = (const float*)d_in[12];
    const float* Wp3  = (const float*)d_in[13];
    float* out = (float*)d_out;

    int n = in_sizes[0];
    int e = in_sizes[1] / 2;
    int v = in_sizes[3] / D;
    int g = out_size / D;

    k_zero<<<512, 256>>>();
    k_embw<<<(v * D + 255) / 256, 256>>>(emb, Wgcn, v);

    int edge_threads = e * 16;
    int edge_blocks = (edge_threads + 255) / 256;
    k_edge_gcn<<<edge_blocks, 256>>>(ei, x, e);
    k_relu1<<<(n * D + 255) / 256, 256>>>(n * D);
    k_edge_scatter<<<edge_blocks, 256>>>(ei, e, 0);            // h1 -> nb
    k_sage<<<(n + 7) / 8, 256>>>(Wsl, Wsr, n);
    k_edge_scatter<<<edge_blocks, 256>>>(ei, e, 1);            // h2 -> agg
    k_gin<<<(n + 7) / 8, 256>>>(Wg1, bg1, Wg2, bg2, n);
    k_pool<<<(n + POOL_CHUNK - 1) / POOL_CHUNK, D>>>(batch, n);
    k_final<<<(g + 7) / 8, 256>>>(Wp1, Wp2, Wp3, out, g);
}

// round 2
// speedup vs baseline: 1.2547x; 1.2547x over previous
#include <cuda_runtime.h>

#define D 64
#define MAXN 50000
#define MAXE 800000
#define MAXG 512
#define MAXV 128
#define SCAN_B 512

// ---------------- scratch (device globals; no allocation) ----------------
__device__ __align__(128) float g_embW[MAXV * D];   // (emb @ W_gcn) hot table
__device__ __align__(128) float g_h1[MAXN * D];
__device__ __align__(128) float g_nb[MAXN * D];     // SAGE mean of neighbors
__device__ __align__(128) float g_h2[MAXN * D];
__device__ __align__(128) float g_z[MAXN * D];      // GIN z = h2 + sum_nb h2
__device__ __align__(128) float g_h3[MAXN * D];
__device__ __align__(128) float g_ps1[MAXG * D];
__device__ __align__(128) float g_ps2[MAXG * D];
__device__ __align__(128) float g_ps3[MAXG * D];
__device__ __align__(128) float g_cnt[MAXG];
// CSR build
__device__ __align__(128) int g_deg[MAXN];
__device__ __align__(128) int g_off[MAXN];     // exclusive prefix of deg
__device__ __align__(128) int g_cursor[MAXN];
__device__ __align__(128) int g_srcs[MAXE];
__device__ __align__(128) int g_bsums[256];
__device__ __align__(128) int g_boff[256];

__device__ __forceinline__ float4 f4add(float4 a, float4 b) {
    return make_float4(a.x + b.x, a.y + b.y, a.z + b.z, a.w + b.w);
}

// ---------------- zero small scratch ----------------
__global__ void k_zero(int n_nodes) {
    int i = blockIdx.x * blockDim.x + threadIdx.x;
    int stride = gridDim.x * blockDim.x;
    for (int j = i; j < n_nodes; j += stride) g_deg[j] = 0;
    for (int j = i; j < MAXG * D; j += stride) { g_ps1[j] = 0.f; g_ps2[j] = 0.f; g_ps3[j] = 0.f; }
    for (int j = i; j < MAXG; j += stride) g_cnt[j] = 0.f;
}

// ---------------- embW = emb @ W_gcn ----------------
__global__ void k_embw(const float* __restrict__ emb, const float* __restrict__ W, int Vn) {
    int idx = blockIdx.x * blockDim.x + threadIdx.x;
    if (idx >= Vn * D) return;
    int v = idx >> 6, j = idx & 63;
    float s = 0.f;
#pragma unroll
    for (int k = 0; k < D; k++) s += emb[v * D + k] * W[k * D + j];
    g_embW[idx] = s;
}

// ---------------- CSR build ----------------
__global__ void k_hist(const int* __restrict__ ei, int E_) {
    int e = blockIdx.x * blockDim.x + threadIdx.x;
    if (e >= E_) return;
    atomicAdd(&g_deg[ei[E_ + e]], 1);
}

// block-level inclusive scan (Hillis-Steele), write exclusive partials + block sums
__global__ void k_scan1(int n) {
    __shared__ int s[SCAN_B];
    int t = threadIdx.x;
    int i = blockIdx.x * SCAN_B + t;
    int v = (i < n) ? g_deg[i] : 0;
    s[t] = v;
    __syncthreads();
#pragma unroll
    for (int off = 1; off < SCAN_B; off <<= 1) {
        int tv = (t >= off) ? s[t - off] : 0;
        __syncthreads();
        s[t] += tv;
        __syncthreads();
    }
    if (i < n) g_off[i] = s[t] - v;  // exclusive within block
    if (t == SCAN_B - 1) g_bsums[blockIdx.x] = s[t];
}

__global__ void k_scan2(int nb) {
    __shared__ int s[256];
    int t = threadIdx.x;
    int v = (t < nb) ? g_bsums[t] : 0;
    s[t] = v;
    __syncthreads();
#pragma unroll
    for (int off = 1; off < 256; off <<= 1) {
        int tv = (t >= off) ? s[t - off] : 0;
        __syncthreads();
        s[t] += tv;
        __syncthreads();
    }
    if (t < nb) g_boff[t] = s[t] - v;  // exclusive
}

__global__ void k_scan3(int n) {
    int i = blockIdx.x * SCAN_B + threadIdx.x;
    if (i >= n) return;
    int o = g_off[i] + g_boff[blockIdx.x];
    g_off[i] = o;
    g_cursor[i] = o;
}

__global__ void k_scatter(const int* __restrict__ ei, int E_) {
    int e = blockIdx.x * blockDim.x + threadIdx.x;
    if (e >= E_) return;
    int src = ei[e];
    int dst = ei[E_ + e];
    int pos = atomicAdd(&g_cursor[dst], 1);
    g_srcs[pos] = src;
}

// ---------------- GCN gather: h1[n] = relu(sum_nb embW[x[src]]) ----------------
__global__ void k_gather_gcn(const int* __restrict__ x, int n_nodes) {
    int gid = blockIdx.x * blockDim.x + threadIdx.x;
    int node = gid >> 4, q = gid & 15;
    if (node >= n_nodes) return;
    int start = g_off[node];
    int cnt = g_deg[node];
    float4 acc = make_float4(0.f, 0.f, 0.f, 0.f);
    for (int t = 0; t < cnt; t++) {
        int s = __ldg(&g_srcs[start + t]);
        int row = __ldg(&x[s]);
        float4 v = reinterpret_cast<const float4*>(g_embW + row * D)[q];
        acc = f4add(acc, v);
    }
    acc.x = fmaxf(acc.x, 0.f); acc.y = fmaxf(acc.y, 0.f);
    acc.z = fmaxf(acc.z, 0.f); acc.w = fmaxf(acc.w, 0.f);
    reinterpret_cast<float4*>(g_h1 + node * D)[q] = acc;
}

// ---------------- SAGE gather: nb[n] = mean_nb h1[src] ----------------
__global__ void k_gather_mean(int n_nodes) {
    int gid = blockIdx.x * blockDim.x + threadIdx.x;
    int node = gid >> 4, q = gid & 15;
    if (node >= n_nodes) return;
    int start = g_off[node];
    int cnt = g_deg[node];
    float4 acc = make_float4(0.f, 0.f, 0.f, 0.f);
    for (int t = 0; t < cnt; t++) {
        int s = __ldg(&g_srcs[start + t]);
        float4 v = reinterpret_cast<const float4*>(g_h1 + s * D)[q];
        acc = f4add(acc, v);
    }
    float invd = 1.0f / fmaxf((float)cnt, 1.0f);
    acc.x *= invd; acc.y *= invd; acc.z *= invd; acc.w *= invd;
    reinterpret_cast<float4*>(g_nb + node * D)[q] = acc;
}

// ---------------- GIN gather: z[n] = h2[n] + sum_nb h2[src] ----------------
__global__ void k_gather_gin(int n_nodes) {
    int gid = blockIdx.x * blockDim.x + threadIdx.x;
    int node = gid >> 4, q = gid & 15;
    if (node >= n_nodes) return;
    int start = g_off[node];
    int cnt = g_deg[node];
    float4 acc = reinterpret_cast<const float4*>(g_h2 + node * D)[q];
    for (int t = 0; t < cnt; t++) {
        int s = __ldg(&g_srcs[start + t]);
        float4 v = reinterpret_cast<const float4*>(g_h2 + s * D)[q];
        acc = f4add(acc, v);
    }
    reinterpret_cast<float4*>(g_z + node * D)[q] = acc;
}

// ---------------- SAGE GEMV: h2 = relu(nb @ Wl + h1 @ Wr) ----------------
__global__ void k_sage(const float* __restrict__ Wl, const float* __restrict__ Wr, int n_nodes) {
    __shared__ float sWl[D * D];
    __shared__ float sWr[D * D];
    for (int i = threadIdx.x; i < D * D; i += blockDim.x) { sWl[i] = Wl[i]; sWr[i] = Wr[i]; }
    __syncthreads();
    int warp = threadIdx.x >> 5, lane = threadIdx.x & 31;
    int n = blockIdx.x * 8 + warp;
    if (n >= n_nodes) return;
    float nb0 = g_nb[n * D + lane];
    float nb1 = g_nb[n * D + lane + 32];
    float h0 = g_h1[n * D + lane];
    float h1v = g_h1[n * D + lane + 32];
    float acc0 = 0.f, acc1 = 0.f;
#pragma unroll
    for (int k = 0; k < 32; k++) {
        float m = __shfl_sync(0xffffffffu, nb0, k);
        float h = __shfl_sync(0xffffffffu, h0, k);
        acc0 += m * sWl[k * D + lane] + h * sWr[k * D + lane];
        acc1 += m * sWl[k * D + lane + 32] + h * sWr[k * D + lane + 32];
    }
#pragma unroll
    for (int k = 0; k < 32; k++) {
        float m = __shfl_sync(0xffffffffu, nb1, k);
        float h = __shfl_sync(0xffffffffu, h1v, k);
        acc0 += m * sWl[(k + 32) * D + lane] + h * sWr[(k + 32) * D + lane];
        acc1 += m * sWl[(k + 32) * D + lane + 32] + h * sWr[(k + 32) * D + lane + 32];
    }
    g_h2[n * D + lane] = fmaxf(acc0, 0.f);
    g_h2[n * D + lane + 32] = fmaxf(acc1, 0.f);
}

// ---------------- GIN MLP: h3 = relu(relu(z@W1+b1)@W2+b2) ----------------
__global__ void k_gin(const float* __restrict__ W1, const float* __restrict__ b1,
                      const float* __restrict__ W2, const float* __restrict__ b2, int n_nodes) {
    __shared__ float sW1[D * D];
    __shared__ float sW2[D * D];
    __shared__ float sb1[D];
    __shared__ float sb2[D];
    for (int i = threadIdx.x; i < D * D; i += blockDim.x) { sW1[i] = W1[i]; sW2[i] = W2[i]; }
    for (int i = threadIdx.x; i < D; i += blockDim.x) { sb1[i] = b1[i]; sb2[i] = b2[i]; }
    __syncthreads();
    int warp = threadIdx.x >> 5, lane = threadIdx.x & 31;
    int n = blockIdx.x * 8 + warp;
    if (n >= n_nodes) return;
    float z0 = g_z[n * D + lane];
    float z1 = g_z[n * D + lane + 32];
    float t0 = sb1[lane], t1 = sb1[lane + 32];
#pragma unroll
    for (int k = 0; k < 32; k++) {
        float z = __shfl_sync(0xffffffffu, z0, k);
        t0 += z * sW1[k * D + lane];
        t1 += z * sW1[k * D + lane + 32];
    }
#pragma unroll
    for (int k = 0; k < 32; k++) {
        float z = __shfl_sync(0xffffffffu, z1, k);
        t0 += z * sW1[(k + 32) * D + lane];
        t1 += z * sW1[(k + 32) * D + lane + 32];
    }
    t0 = fmaxf(t0, 0.f);
    t1 = fmaxf(t1, 0.f);
    float o0 = sb2[lane], o1 = sb2[lane + 32];
#pragma unroll
    for (int k = 0; k < 32; k++) {
        float t = __shfl_sync(0xffffffffu, t0, k);
        o0 += t * sW2[k * D + lane];
        o1 += t * sW2[k * D + lane + 32];
    }
#pragma unroll
    for (int k = 0; k < 32; k++) {
        float t = __shfl_sync(0xffffffffu, t1, k);
        o0 += t * sW2[(k + 32) * D + lane];
        o1 += t * sW2[(k + 32) * D + lane + 32];
    }
    g_h3[n * D + lane] = fmaxf(o0, 0.f);
    g_h3[n * D + lane + 32] = fmaxf(o1, 0.f);
}

// ---------------- pooling: batch sorted -> run flushing ----------------
#define POOL_CHUNK 64
__global__ void k_pool(const int* __restrict__ batch, int n_nodes) {
    int j = threadIdx.x;  // 0..63
    int n0 = blockIdx.x * POOL_CHUNK;
    int nend = n0 + POOL_CHUNK;
    if (nend > n_nodes) nend = n_nodes;
    int g = -1;
    float s1 = 0.f, s2 = 0.f, s3 = 0.f, c = 0.f;
    for (int n = n0; n < nend; n++) {
        int bg = batch[n];
        if (bg != g) {
            if (g >= 0) {
                atomicAdd(&g_ps1[g * D + j], s1);
                atomicAdd(&g_ps2[g * D + j], s2);
                atomicAdd(&g_ps3[g * D + j], s3);
                if (j == 0) atomicAdd(&g_cnt[g], c);
            }
            g = bg; s1 = s2 = s3 = 0.f; c = 0.f;
        }
        s1 += g_h1[n * D + j];
        s2 += g_h2[n * D + j];
        s3 += g_h3[n * D + j];
        c += 1.0f;
    }
    if (g >= 0) {
        atomicAdd(&g_ps1[g * D + j], s1);
        atomicAdd(&g_ps2[g * D + j], s2);
        atomicAdd(&g_ps3[g * D + j], s3);
        if (j == 0) atomicAdd(&g_cnt[g], c);
    }
}

// ---------------- final ----------------
__global__ void k_final(const float* __restrict__ Wp1, const float* __restrict__ Wp2,
                        const float* __restrict__ Wp3, float* __restrict__ out, int Gn) {
    __shared__ float s1[D * D];
    __shared__ float s2[D * D];
    __shared__ float s3[D * D];
    for (int i = threadIdx.x; i < D * D; i += blockDim.x) { s1[i] = Wp1[i]; s2[i] = Wp2[i]; s3[i] = Wp3[i]; }
    __syncthreads();
    int warp = threadIdx.x >> 5, lane = threadIdx.x & 31;
    int g = blockIdx.x * 8 + warp;
    if (g >= Gn) return;
    float ic = 1.0f / fmaxf(g_cnt[g], 1.0f);
    float a0 = g_ps1[g * D + lane] * ic, a1 = g_ps1[g * D + lane + 32] * ic;
    float b0 = g_ps2[g * D + lane] * ic, b1 = g_ps2[g * D + lane + 32] * ic;
    float c0 = g_ps3[g * D + lane] * ic, c1 = g_ps3[g * D + lane + 32] * ic;
    float acc0 = 0.f, acc1 = 0.f;
#pragma unroll
    for (int k = 0; k < 32; k++) {
        float va = __shfl_sync(0xffffffffu, a0, k);
        float vb = __shfl_sync(0xffffffffu, b0, k);
        float vc = __shfl_sync(0xffffffffu, c0, k);
        acc0 += va * s1[k * D + lane] + vb * s2[k * D + lane] + vc * s3[k * D + lane];
        acc1 += va * s1[k * D + lane + 32] + vb * s2[k * D + lane + 32] + vc * s3[k * D + lane + 32];
    }
#pragma unroll
    for (int k = 0; k < 32; k++) {
        float va = __shfl_sync(0xffffffffu, a1, k);
        float vb = __shfl_sync(0xffffffffu, b1, k);
        float vc = __shfl_sync(0xffffffffu, c1, k);
        acc0 += va * s1[(k + 32) * D + lane] + vb * s2[(k + 32) * D + lane] + vc * s3[(k + 32) * D + lane];
        acc1 += va * s1[(k + 32) * D + lane + 32] + vb * s2[(k + 32) * D + lane + 32] + vc * s3[(k + 32) * D + lane + 32];
    }
    out[g * D + lane] = fmaxf(acc0, 0.f);
    out[g * D + lane + 32] = fmaxf(acc1, 0.f);
}

// ---------------- launch ----------------
extern "C" void kernel_launch(void* const* d_in, const int* in_sizes, int n_in,
                              void* d_out, int out_size) {
    const int* x      = (const int*)d_in[0];
    const int* ei     = (const int*)d_in[1];
    const int* batch  = (const int*)d_in[2];
    const float* emb  = (const float*)d_in[3];
    const float* Wgcn = (const float*)d_in[4];
    const float* Wsl  = (const float*)d_in[5];
    const float* Wsr  = (const float*)d_in[6];
    const float* Wg1  = (const float*)d_in[7];
    const float* bg1  = (const float*)d_in[8];
    const float* Wg2  = (const float*)d_in[9];
    const float* bg2  = (const float*)d_in[10];
    const float* Wp1  = (const float*)d_in[11];
    const float* Wp2  = (const float*)d_in[12];
    const float* Wp3  = (const float*)d_in[13];
    float* out = (float*)d_out;

    int n = in_sizes[0];
    int e = in_sizes[1] / 2;
    int v = in_sizes[3] / D;
    int g = out_size / D;

    int nb = (n + SCAN_B - 1) / SCAN_B;

    k_zero<<<256, 256>>>(n);
    k_embw<<<(v * D + 255) / 256, 256>>>(emb, Wgcn, v);
    k_hist<<<(e + 255) / 256, 256>>>(ei, e);
    k_scan1<<<nb, SCAN_B>>>(n);
    k_scan2<<<1, 256>>>(nb);
    k_scan3<<<nb, SCAN_B>>>(n);
    k_scatter<<<(e + 255) / 256, 256>>>(ei, e);

    int gth = n * 16;
    int gblk = (gth + 255) / 256;
    k_gather_gcn<<<gblk, 256>>>(x, n);
    k_gather_mean<<<gblk, 256>>>(n);
    k_sage<<<(n + 7) / 8, 256>>>(Wsl, Wsr, n);
    k_gather_gin<<<gblk, 256>>>(n);
    k_gin<<<(n + 7) / 8, 256>>>(Wg1, bg1, Wg2, bg2, n);
    k_pool<<<(n + POOL_CHUNK - 1) / POOL_CHUNK, D>>>(batch, n);
    k_final<<<(g + 7) / 8, 256>>>(Wp1, Wp2, Wp3, out, g);
}

// round 3
// speedup vs baseline: 1.2967x; 1.0335x over previous
#include <cuda_runtime.h>

#define D 64
#define MAXN 50000
#define MAXE 800000
#define MAXG 512
#define MAXV 128
#define SCAN_B 512

// ---------------- scratch (device globals; no allocation) ----------------
__device__ __align__(128) float g_embW[MAXV * D];
__device__ __align__(128) float g_h1[MAXN * D];
__device__ __align__(128) float g_h2[MAXN * D];
__device__ __align__(128) float g_h3[MAXN * D];
__device__ __align__(128) float g_ps1[MAXG * D];
__device__ __align__(128) float g_ps2[MAXG * D];
__device__ __align__(128) float g_ps3[MAXG * D];
__device__ __align__(128) float g_cnt[MAXG];
// CSR build
__device__ __align__(128) int g_deg[MAXN];
__device__ __align__(128) int g_off[MAXN];
__device__ __align__(128) int g_cursor[MAXN];
__device__ __align__(128) int g_srcs[MAXE];
__device__ __align__(128) int g_bsums[256];
__device__ __align__(128) int g_boff[256];

__device__ __forceinline__ float4 f4add(float4 a, float4 b) {
    return make_float4(a.x + b.x, a.y + b.y, a.z + b.z, a.w + b.w);
}

// ---------------- init: zero deg/pools + embW = emb @ W_gcn ----------------
__global__ void k_init(const float* __restrict__ emb, const float* __restrict__ W,
                       int Vn, int n_nodes) {
    int i = blockIdx.x * blockDim.x + threadIdx.x;
    int stride = gridDim.x * blockDim.x;
    for (int j = i; j < n_nodes; j += stride) g_deg[j] = 0;
    for (int j = i; j < MAXG * D; j += stride) { g_ps1[j] = 0.f; g_ps2[j] = 0.f; g_ps3[j] = 0.f; }
    for (int j = i; j < MAXG; j += stride) g_cnt[j] = 0.f;
    for (int idx = i; idx < Vn * D; idx += stride) {
        int v = idx >> 6, j = idx & 63;
        float s = 0.f;
#pragma unroll
        for (int k = 0; k < D; k++) s += emb[v * D + k] * W[k * D + j];
        g_embW[idx] = s;
    }
}

// ---------------- CSR build ----------------
__global__ void k_hist(const int* __restrict__ ei, int E_) {
    int e = blockIdx.x * blockDim.x + threadIdx.x;
    if (e >= E_) return;
    atomicAdd(&g_deg[ei[E_ + e]], 1);
}

// warp-shuffle block scan: exclusive prefix within block + block sum
__global__ void k_scan1(int n) {
    __shared__ int warp_sums[16];
    int t = threadIdx.x, lane = t & 31, warp = t >> 5;
    int i = blockIdx.x * SCAN_B + t;
    int v = (i < n) ? g_deg[i] : 0;
    int inc = v;
#pragma unroll
    for (int off = 1; off < 32; off <<= 1) {
        int tv = __shfl_up_sync(0xffffffffu, inc, off);
        if (lane >= off) inc += tv;
    }
    if (lane == 31) warp_sums[warp] = inc;
    __syncthreads();
    if (warp == 0 && lane < 16) {
        int ws = warp_sums[lane];
        int wi = ws;
#pragma unroll
        for (int off = 1; off < 16; off <<= 1) {
            int tv = __shfl_up_sync(0xffffu, wi, off);
            if (lane >= off) wi += tv;
        }
        warp_sums[lane] = wi - ws;  // exclusive warp offsets
        if (lane == 15) g_bsums[blockIdx.x] = wi;
    }
    __syncthreads();
    if (i < n) g_off[i] = inc - v + warp_sums[warp];
}

__global__ void k_scan2(int nb) {
    // single warp, serial chunks of 32 with carry
    int lane = threadIdx.x;
    int carry = 0;
    for (int base = 0; base < nb; base += 32) {
        int idx = base + lane;
        int v = (idx < nb) ? g_bsums[idx] : 0;
        int inc = v;
#pragma unroll
        for (int off = 1; off < 32; off <<= 1) {
            int tv = __shfl_up_sync(0xffffffffu, inc, off);
            if (lane >= off) inc += tv;
        }
        if (idx < nb) g_boff[idx] = carry + inc - v;
        carry += __shfl_sync(0xffffffffu, inc, 31);
    }
}

__global__ void k_scan3(int n) {
    int i = blockIdx.x * SCAN_B + threadIdx.x;
    if (i >= n) return;
    int o = g_off[i] + g_boff[blockIdx.x];
    g_off[i] = o;
    g_cursor[i] = o;
}

__global__ void k_scatter(const int* __restrict__ ei, int E_) {
    int e = blockIdx.x * blockDim.x + threadIdx.x;
    if (e >= E_) return;
    int src = ei[e];
    int dst = ei[E_ + e];
    int pos = atomicAdd(&g_cursor[dst], 1);
    g_srcs[pos] = src;
}

// ---------------- GCN gather: h1[n] = relu(sum_nb embW[x[src]]) ----------------
// 16 threads/node, 4-deep pipelined. embW is 32KB -> L1-resident.
__global__ void k_gather_gcn(const int* __restrict__ x, int n_nodes) {
    int gid = blockIdx.x * blockDim.x + threadIdx.x;
    int node = gid >> 4, q = gid & 15;
    if (node >= n_nodes) return;
    int start = g_off[node];
    int cnt = g_deg[node];
    const float4* embW4 = reinterpret_cast<const float4*>(g_embW);
    float4 acc = make_float4(0.f, 0.f, 0.f, 0.f);
    int t = 0;
    for (; t + 4 <= cnt; t += 4) {
        int s0 = __ldg(&g_srcs[start + t]);
        int s1 = __ldg(&g_srcs[start + t + 1]);
        int s2 = __ldg(&g_srcs[start + t + 2]);
        int s3 = __ldg(&g_srcs[start + t + 3]);
        int r0 = __ldg(&x[s0]), r1 = __ldg(&x[s1]), r2 = __ldg(&x[s2]), r3 = __ldg(&x[s3]);
        float4 v0 = embW4[r0 * 16 + q];
        float4 v1 = embW4[r1 * 16 + q];
        float4 v2 = embW4[r2 * 16 + q];
        float4 v3 = embW4[r3 * 16 + q];
        acc = f4add(acc, f4add(f4add(v0, v1), f4add(v2, v3)));
    }
    for (; t < cnt; t++) {
        int s = __ldg(&g_srcs[start + t]);
        int r = __ldg(&x[s]);
        acc = f4add(acc, embW4[r * 16 + q]);
    }
    acc.x = fmaxf(acc.x, 0.f); acc.y = fmaxf(acc.y, 0.f);
    acc.z = fmaxf(acc.z, 0.f); acc.w = fmaxf(acc.w, 0.f);
    reinterpret_cast<float4*>(g_h1 + node * D)[q] = acc;
}

// ---------------- fused SAGE: warp/node gather mean(h1) + GEMV ----------------
// h2 = relu(mean_nb(h1) @ Wl + h1 @ Wr). Persistent grid: weights loaded once/block.
__global__ void k_sage(const float* __restrict__ Wl, const float* __restrict__ Wr, int n_nodes) {
    __shared__ float sWl[D * D];
    __shared__ float sWr[D * D];
    for (int i = threadIdx.x; i < D * D; i += blockDim.x) { sWl[i] = Wl[i]; sWr[i] = Wr[i]; }
    __syncthreads();
    int warp = threadIdx.x >> 5, lane = threadIdx.x & 31;
    for (int n = blockIdx.x * 8 + warp; n < n_nodes; n += gridDim.x * 8) {
        int start = g_off[n];
        int cnt = g_deg[n];
        float nb0 = 0.f, nb1 = 0.f;
        int t = 0;
        for (; t + 4 <= cnt; t += 4) {
            int s0 = __ldg(&g_srcs[start + t]);
            int s1 = __ldg(&g_srcs[start + t + 1]);
            int s2 = __ldg(&g_srcs[start + t + 2]);
            int s3 = __ldg(&g_srcs[start + t + 3]);
            float a0 = g_h1[s0 * D + lane], b0 = g_h1[s0 * D + lane + 32];
            float a1 = g_h1[s1 * D + lane], b1 = g_h1[s1 * D + lane + 32];
            float a2 = g_h1[s2 * D + lane], b2 = g_h1[s2 * D + lane + 32];
            float a3 = g_h1[s3 * D + lane], b3 = g_h1[s3 * D + lane + 32];
            nb0 += (a0 + a1) + (a2 + a3);
            nb1 += (b0 + b1) + (b2 + b3);
        }
        for (; t < cnt; t++) {
            int s = __ldg(&g_srcs[start + t]);
            nb0 += g_h1[s * D + lane];
            nb1 += g_h1[s * D + lane + 32];
        }
        float invd = 1.0f / fmaxf((float)cnt, 1.0f);
        nb0 *= invd; nb1 *= invd;
        float h0 = g_h1[n * D + lane];
        float h1v = g_h1[n * D + lane + 32];
        float acc0 = 0.f, acc1 = 0.f;
#pragma unroll
        for (int k = 0; k < 32; k++) {
            float m = __shfl_sync(0xffffffffu, nb0, k);
            float h = __shfl_sync(0xffffffffu, h0, k);
            acc0 += m * sWl[k * D + lane] + h * sWr[k * D + lane];
            acc1 += m * sWl[k * D + lane + 32] + h * sWr[k * D + lane + 32];
        }
#pragma unroll
        for (int k = 0; k < 32; k++) {
            float m = __shfl_sync(0xffffffffu, nb1, k);
            float h = __shfl_sync(0xffffffffu, h1v, k);
            acc0 += m * sWl[(k + 32) * D + lane] + h * sWr[(k + 32) * D + lane];
            acc1 += m * sWl[(k + 32) * D + lane + 32] + h * sWr[(k + 32) * D + lane + 32];
        }
        g_h2[n * D + lane] = fmaxf(acc0, 0.f);
        g_h2[n * D + lane + 32] = fmaxf(acc1, 0.f);
    }
}

// ---------------- fused GIN: warp/node gather sum(h2)+self + 2-layer MLP ----------------
__global__ void k_gin(const float* __restrict__ W1, const float* __restrict__ b1,
                      const float* __restrict__ W2, const float* __restrict__ b2, int n_nodes) {
    __shared__ float sW1[D * D];
    __shared__ float sW2[D * D];
    __shared__ float sb1[D];
    __shared__ float sb2[D];
    for (int i = threadIdx.x; i < D * D; i += blockDim.x) { sW1[i] = W1[i]; sW2[i] = W2[i]; }
    for (int i = threadIdx.x; i < D; i += blockDim.x) { sb1[i] = b1[i]; sb2[i] = b2[i]; }
    __syncthreads();
    int warp = threadIdx.x >> 5, lane = threadIdx.x & 31;
    for (int n = blockIdx.x * 8 + warp; n < n_nodes; n += gridDim.x * 8) {
        int start = g_off[n];
        int cnt = g_deg[n];
        float z0 = g_h2[n * D + lane];
        float z1 = g_h2[n * D + lane + 32];
        int t = 0;
        for (; t + 4 <= cnt; t += 4) {
            int s0 = __ldg(&g_srcs[start + t]);
            int s1 = __ldg(&g_srcs[start + t + 1]);
            int s2 = __ldg(&g_srcs[start + t + 2]);
            int s3 = __ldg(&g_srcs[start + t + 3]);
            float a0 = g_h2[s0 * D + lane], c0 = g_h2[s0 * D + lane + 32];
            float a1 = g_h2[s1 * D + lane], c1 = g_h2[s1 * D + lane + 32];
            float a2 = g_h2[s2 * D + lane], c2 = g_h2[s2 * D + lane + 32];
            float a3 = g_h2[s3 * D + lane], c3 = g_h2[s3 * D + lane + 32];
            z0 += (a0 + a1) + (a2 + a3);
            z1 += (c0 + c1) + (c2 + c3);
        }
        for (; t < cnt; t++) {
            int s = __ldg(&g_srcs[start + t]);
            z0 += g_h2[s * D + lane];
            z1 += g_h2[s * D + lane + 32];
        }
        float t0 = sb1[lane], t1 = sb1[lane + 32];
#pragma unroll
        for (int k = 0; k < 32; k++) {
            float z = __shfl_sync(0xffffffffu, z0, k);
            t0 += z * sW1[k * D + lane];
            t1 += z * sW1[k * D + lane + 32];
        }
#pragma unroll
        for (int k = 0; k < 32; k++) {
            float z = __shfl_sync(0xffffffffu, z1, k);
            t0 += z * sW1[(k + 32) * D + lane];
            t1 += z * sW1[(k + 32) * D + lane + 32];
        }
        t0 = fmaxf(t0, 0.f);
        t1 = fmaxf(t1, 0.f);
        float o0 = sb2[lane], o1 = sb2[lane + 32];
#pragma unroll
        for (int k = 0; k < 32; k++) {
            float tt = __shfl_sync(0xffffffffu, t0, k);
            o0 += tt * sW2[k * D + lane];
            o1 += tt * sW2[k * D + lane + 32];
        }
#pragma unroll
        for (int k = 0; k < 32; k++) {
            float tt = __shfl_sync(0xffffffffu, t1, k);
            o0 += tt * sW2[(k + 32) * D + lane];
            o1 += tt * sW2[(k + 32) * D + lane + 32];
        }
        g_h3[n * D + lane] = fmaxf(o0, 0.f);
        g_h3[n * D + lane + 32] = fmaxf(o1, 0.f);
    }
}

// ---------------- pooling: batch sorted -> run flushing ----------------
#define POOL_CHUNK 64
__global__ void k_pool(const int* __restrict__ batch, int n_nodes) {
    int j = threadIdx.x;  // 0..63
    int n0 = blockIdx.x * POOL_CHUNK;
    int nend = n0 + POOL_CHUNK;
    if (nend > n_nodes) nend = n_nodes;
    int g = -1;
    float s1 = 0.f, s2 = 0.f, s3 = 0.f, c = 0.f;
    for (int n = n0; n < nend; n++) {
        int bg = batch[n];
        if (bg != g) {
            if (g >= 0) {
                atomicAdd(&g_ps1[g * D + j], s1);
                atomicAdd(&g_ps2[g * D + j], s2);
                atomicAdd(&g_ps3[g * D + j], s3);
                if (j == 0) atomicAdd(&g_cnt[g], c);
            }
            g = bg; s1 = s2 = s3 = 0.f; c = 0.f;
        }
        s1 += g_h1[n * D + j];
        s2 += g_h2[n * D + j];
        s3 += g_h3[n * D + j];
        c += 1.0f;
    }
    if (g >= 0) {
        atomicAdd(&g_ps1[g * D + j], s1);
        atomicAdd(&g_ps2[g * D + j], s2);
        atomicAdd(&g_ps3[g * D + j], s3);
        if (j == 0) atomicAdd(&g_cnt[g], c);
    }
}

// ---------------- final ----------------
__global__ void k_final(const float* __restrict__ Wp1, const float* __restrict__ Wp2,
                        const float* __restrict__ Wp3, float* __restrict__ out, int Gn) {
    __shared__ float s1[D * D];
    __shared__ float s2[D * D];
    __shared__ float s3[D * D];
    for (int i = threadIdx.x; i < D * D; i += blockDim.x) { s1[i] = Wp1[i]; s2[i] = Wp2[i]; s3[i] = Wp3[i]; }
    __syncthreads();
    int warp = threadIdx.x >> 5, lane = threadIdx.x & 31;
    int g = blockIdx.x * 8 + warp;
    if (g >= Gn) return;
    float ic = 1.0f / fmaxf(g_cnt[g], 1.0f);
    float a0 = g_ps1[g * D + lane] * ic, a1 = g_ps1[g * D + lane + 32] * ic;
    float b0 = g_ps2[g * D + lane] * ic, b1 = g_ps2[g * D + lane + 32] * ic;
    float c0 = g_ps3[g * D + lane] * ic, c1 = g_ps3[g * D + lane + 32] * ic;
    float acc0 = 0.f, acc1 = 0.f;
#pragma unroll
    for (int k = 0; k < 32; k++) {
        float va = __shfl_sync(0xffffffffu, a0, k);
        float vb = __shfl_sync(0xffffffffu, b0, k);
        float vc = __shfl_sync(0xffffffffu, c0, k);
        acc0 += va * s1[k * D + lane] + vb * s2[k * D + lane] + vc * s3[k * D + lane];
        acc1 += va * s1[k * D + lane + 32] + vb * s2[k * D + lane + 32] + vc * s3[k * D + lane + 32];
    }
#pragma unroll
    for (int k = 0; k < 32; k++) {
        float va = __shfl_sync(0xffffffffu, a1, k);
        float vb = __shfl_sync(0xffffffffu, b1, k);
        float vc = __shfl_sync(0xffffffffu, c1, k);
        acc0 += va * s1[(k + 32) * D + lane] + vb * s2[(k + 32) * D + lane] + vc * s3[(k + 32) * D + lane];
        acc1 += va * s1[(k + 32) * D + lane + 32] + vb * s2[(k + 32) * D + lane + 32] + vc * s3[(k + 32) * D + lane + 32];
    }
    out[g * D + lane] = fmaxf(acc0, 0.f);
    out[g * D + lane + 32] = fmaxf(acc1, 0.f);
}

// ---------------- launch ----------------
extern "C" void kernel_launch(void* const* d_in, const int* in_sizes, int n_in,
                              void* d_out, int out_size) {
    const int* x      = (const int*)d_in[0];
    const int* ei     = (const int*)d_in[1];
    const int* batch  = (const int*)d_in[2];
    const float* emb  = (const float*)d_in[3];
    const float* Wgcn = (const float*)d_in[4];
    const float* Wsl  = (const float*)d_in[5];
    const float* Wsr  = (const float*)d_in[6];
    const float* Wg1  = (const float*)d_in[7];
    const float* bg1  = (const float*)d_in[8];
    const float* Wg2  = (const float*)d_in[9];
    const float* bg2  = (const float*)d_in[10];
    const float* Wp1  = (const float*)d_in[11];
    const float* Wp2  = (const float*)d_in[12];
    const float* Wp3  = (const float*)d_in[13];
    float* out = (float*)d_out;

    int n = in_sizes[0];
    int e = in_sizes[1] / 2;
    int v = in_sizes[3] / D;
    int g = out_size / D;

    int nb = (n + SCAN_B - 1) / SCAN_B;

    k_init<<<256, 256>>>(emb, Wgcn, v, n);
    k_hist<<<(e + 255) / 256, 256>>>(ei, e);
    k_scan1<<<nb, SCAN_B>>>(n);
    k_scan2<<<1, 32>>>(nb);
    k_scan3<<<nb, SCAN_B>>>(n);
    k_scatter<<<(e + 255) / 256, 256>>>(ei, e);

    int gth = n * 16;
    int gblk = (gth + 255) / 256;
    k_gather_gcn<<<gblk, 256>>>(x, n);

    int pgrid = 1184;  // persistent-ish: 8 blocks/SM
    int need = (n + 7) / 8;
    if (pgrid > need) pgrid = need;
    k_sage<<<pgrid, 256>>>(Wsl, Wsr, n);
    k_gin<<<pgrid, 256>>>(Wg1, bg1, Wg2, bg2, n);
    k_pool<<<(n + POOL_CHUNK - 1) / POOL_CHUNK, D>>>(batch, n);
    k_final<<<(g + 7) / 8, 256>>>(Wp1, Wp2, Wp3, out, g);
}

// round 4
// speedup vs baseline: 1.3920x; 1.0734x over previous
#include <cuda_runtime.h>

#define D 64
#define MAXN 50000
#define MAXE 800000
#define MAXG 512
#define MAXV 128

typedef unsigned long long u64;

// ---------------- scratch (device globals; no allocation) ----------------
__device__ __align__(128) float g_embW[MAXV * D];
__device__ __align__(128) float g_h1[MAXN * D];
__device__ __align__(128) float g_nb[MAXN * D];   // SAGE mean; later GIN t-stage scratch
__device__ __align__(128) float g_h2[MAXN * D];
__device__ __align__(128) float g_z[MAXN * D];
__device__ __align__(128) float g_h3[MAXN * D];
__device__ __align__(128) float g_ps1[MAXG * D];
__device__ __align__(128) float g_ps2[MAXG * D];
__device__ __align__(128) float g_ps3[MAXG * D];
__device__ __align__(128) float g_cnt[MAXG];
// CSR build
__device__ __align__(128) int g_deg[MAXN];
__device__ __align__(128) int g_off[MAXN];
__device__ __align__(128) int g_cursor[MAXN];
__device__ __align__(128) int g_srcs[MAXE];

__device__ __forceinline__ float4 f4add(float4 a, float4 b) {
    return make_float4(a.x + b.x, a.y + b.y, a.z + b.z, a.w + b.w);
}

// packed f32x2 helpers (Blackwell)
__device__ __forceinline__ u64 pack2s(float x) {
    u64 r; asm("mov.b64 %0, {%1,%1};" : "=l"(r) : "f"(x)); return r;
}
__device__ __forceinline__ u64 pack2(float x, float y) {
    u64 r; asm("mov.b64 %0, {%1,%2};" : "=l"(r) : "f"(x), "f"(y)); return r;
}
__device__ __forceinline__ void ffma2(u64& d, u64 a, u64 b) {
    asm("fma.rn.f32x2 %0, %1, %2, %3;" : "=l"(d) : "l"(a), "l"(b), "l"(d));
}
__device__ __forceinline__ float2 unpack2(u64 v) {
    float2 f; asm("mov.b64 {%0,%1}, %2;" : "=f"(f.x), "=f"(f.y) : "l"(v)); return f;
}

// ---------------- init: zero deg/pools + embW = emb @ W_gcn ----------------
__global__ void k_init(const float* __restrict__ emb, const float* __restrict__ W,
                       int Vn, int n_nodes) {
    int i = blockIdx.x * blockDim.x + threadIdx.x;
    int stride = gridDim.x * blockDim.x;
    for (int j = i; j < n_nodes; j += stride) g_deg[j] = 0;
    for (int j = i; j < MAXG * D; j += stride) { g_ps1[j] = 0.f; g_ps2[j] = 0.f; g_ps3[j] = 0.f; }
    for (int j = i; j < MAXG; j += stride) g_cnt[j] = 0.f;
    for (int idx = i; idx < Vn * D; idx += stride) {
        int v = idx >> 6, j = idx & 63;
        float s = 0.f;
#pragma unroll
        for (int k = 0; k < D; k++) s += emb[v * D + k] * W[k * D + j];
        g_embW[idx] = s;
    }
}

// ---------------- CSR build ----------------
__global__ void k_hist(const int* __restrict__ ei, int E_) {
    int e = blockIdx.x * blockDim.x + threadIdx.x;
    if (e >= E_) return;
    atomicAdd(&g_deg[ei[E_ + e]], 1);
}

// single-block exclusive scan over g_deg -> g_off, g_cursor
__global__ void k_scan(int n) {
    __shared__ int wsum[32];
    __shared__ int s_total;
    int tid = threadIdx.x, lane = tid & 31, warp = tid >> 5;
    int carry = 0;
    for (int base = 0; base < n; base += 1024) {
        int i = base + tid;
        int v = (i < n) ? g_deg[i] : 0;
        int inc = v;
#pragma unroll
        for (int off = 1; off < 32; off <<= 1) {
            int tv = __shfl_up_sync(0xffffffffu, inc, off);
            if (lane >= off) inc += tv;
        }
        if (lane == 31) wsum[warp] = inc;
        __syncthreads();
        if (warp == 0) {
            int w = wsum[lane];
            int wi = w;
#pragma unroll
            for (int off = 1; off < 32; off <<= 1) {
                int tv = __shfl_up_sync(0xffffffffu, wi, off);
                if (lane >= off) wi += tv;
            }
            wsum[lane] = wi - w;
            if (lane == 31) s_total = wi;
        }
        __syncthreads();
        if (i < n) {
            int o = carry + inc - v + wsum[warp];
            g_off[i] = o;
            g_cursor[i] = o;
        }
        carry += s_total;
        __syncthreads();
    }
}

__global__ void k_scatter(const int* __restrict__ ei, int E_) {
    int e = blockIdx.x * blockDim.x + threadIdx.x;
    if (e >= E_) return;
    int src = ei[e];
    int dst = ei[E_ + e];
    int pos = atomicAdd(&g_cursor[dst], 1);
    g_srcs[pos] = src;
}

// ---------------- GCN gather: h1[n] = relu(sum_nb embW[x[src]]) ----------------
__global__ void k_gather_gcn(const int* __restrict__ x, int n_nodes) {
    int gid = blockIdx.x * blockDim.x + threadIdx.x;
    int node = gid >> 4, q = gid & 15;
    if (node >= n_nodes) return;
    int start = g_off[node];
    int cnt = g_deg[node];
    const float4* embW4 = reinterpret_cast<const float4*>(g_embW);
    float4 acc = make_float4(0.f, 0.f, 0.f, 0.f);
    int t = 0;
    for (; t + 4 <= cnt; t += 4) {
        int s0 = __ldg(&g_srcs[start + t]);
        int s1 = __ldg(&g_srcs[start + t + 1]);
        int s2 = __ldg(&g_srcs[start + t + 2]);
        int s3 = __ldg(&g_srcs[start + t + 3]);
        int r0 = __ldg(&x[s0]), r1 = __ldg(&x[s1]), r2 = __ldg(&x[s2]), r3 = __ldg(&x[s3]);
        float4 v0 = embW4[r0 * 16 + q];
        float4 v1 = embW4[r1 * 16 + q];
        float4 v2 = embW4[r2 * 16 + q];
        float4 v3 = embW4[r3 * 16 + q];
        acc = f4add(acc, f4add(f4add(v0, v1), f4add(v2, v3)));
    }
    for (; t < cnt; t++) {
        int s = __ldg(&g_srcs[start + t]);
        int r = __ldg(&x[s]);
        acc = f4add(acc, embW4[r * 16 + q]);
    }
    acc.x = fmaxf(acc.x, 0.f); acc.y = fmaxf(acc.y, 0.f);
    acc.z = fmaxf(acc.z, 0.f); acc.w = fmaxf(acc.w, 0.f);
    reinterpret_cast<float4*>(g_h1 + node * D)[q] = acc;
}

// ---------------- SAGE gather: nb[n] = mean_nb h1[src] ----------------
__global__ void k_gather_mean(int n_nodes) {
    int gid = blockIdx.x * blockDim.x + threadIdx.x;
    int node = gid >> 4, q = gid & 15;
    if (node >= n_nodes) return;
    int start = g_off[node];
    int cnt = g_deg[node];
    float4 acc = make_float4(0.f, 0.f, 0.f, 0.f);
    int t = 0;
    for (; t + 4 <= cnt; t += 4) {
        int s0 = __ldg(&g_srcs[start + t]);
        int s1 = __ldg(&g_srcs[start + t + 1]);
        int s2 = __ldg(&g_srcs[start + t + 2]);
        int s3 = __ldg(&g_srcs[start + t + 3]);
        float4 v0 = reinterpret_cast<const float4*>(g_h1 + s0 * D)[q];
        float4 v1 = reinterpret_cast<const float4*>(g_h1 + s1 * D)[q];
        float4 v2 = reinterpret_cast<const float4*>(g_h1 + s2 * D)[q];
        float4 v3 = reinterpret_cast<const float4*>(g_h1 + s3 * D)[q];
        acc = f4add(acc, f4add(f4add(v0, v1), f4add(v2, v3)));
    }
    for (; t < cnt; t++) {
        int s = __ldg(&g_srcs[start + t]);
        acc = f4add(acc, reinterpret_cast<const float4*>(g_h1 + s * D)[q]);
    }
    float invd = 1.0f / fmaxf((float)cnt, 1.0f);
    acc.x *= invd; acc.y *= invd; acc.z *= invd; acc.w *= invd;
    reinterpret_cast<float4*>(g_nb + node * D)[q] = acc;
}

// ---------------- GIN gather: z[n] = h2[n] + sum_nb h2[src] ----------------
__global__ void k_gather_gin(int n_nodes) {
    int gid = blockIdx.x * blockDim.x + threadIdx.x;
    int node = gid >> 4, q = gid & 15;
    if (node >= n_nodes) return;
    int start = g_off[node];
    int cnt = g_deg[node];
    float4 acc = reinterpret_cast<const float4*>(g_h2 + node * D)[q];
    int t = 0;
    for (; t + 4 <= cnt; t += 4) {
        int s0 = __ldg(&g_srcs[start + t]);
        int s1 = __ldg(&g_srcs[start + t + 1]);
        int s2 = __ldg(&g_srcs[start + t + 2]);
        int s3 = __ldg(&g_srcs[start + t + 3]);
        float4 v0 = reinterpret_cast<const float4*>(g_h2 + s0 * D)[q];
        float4 v1 = reinterpret_cast<const float4*>(g_h2 + s1 * D)[q];
        float4 v2 = reinterpret_cast<const float4*>(g_h2 + s2 * D)[q];
        float4 v3 = reinterpret_cast<const float4*>(g_h2 + s3 * D)[q];
        acc = f4add(acc, f4add(f4add(v0, v1), f4add(v2, v3)));
    }
    for (; t < cnt; t++) {
        int s = __ldg(&g_srcs[start + t]);
        acc = f4add(acc, reinterpret_cast<const float4*>(g_h2 + s * D)[q]);
    }
    reinterpret_cast<float4*>(g_z + node * D)[q] = acc;
}

// ---------------- SAGE GEMM: h2 = relu(nb @ Wl + h1 @ Wr) ----------------
// lane = node; weights broadcast from SMEM; f32x2 packed accumulators.
__global__ void __launch_bounds__(256) k_sage(const float* __restrict__ Wl,
                                              const float* __restrict__ Wr, int n_nodes) {
    __shared__ ulonglong2 sWl[D * 16];
    __shared__ ulonglong2 sWr[D * 16];
    {
        const ulonglong2* wl2 = reinterpret_cast<const ulonglong2*>(Wl);
        const ulonglong2* wr2 = reinterpret_cast<const ulonglong2*>(Wr);
        for (int i = threadIdx.x; i < D * 16; i += blockDim.x) { sWl[i] = wl2[i]; sWr[i] = wr2[i]; }
    }
    __syncthreads();
    int lane = threadIdx.x & 31, warp = threadIdx.x >> 5;
    int ntiles = (n_nodes + 31) / 32;
    int nwarps = gridDim.x * 8;
    for (int tile = blockIdx.x * 8 + warp; tile < ntiles; tile += nwarps) {
        int n = tile * 32 + lane;
        bool valid = n < n_nodes;
        int nn = valid ? n : (n_nodes - 1);
        const float4* nb4 = reinterpret_cast<const float4*>(g_nb + nn * D);
        const float4* h4 = reinterpret_cast<const float4*>(g_h1 + nn * D);
        u64 acc[32];
#pragma unroll
        for (int j = 0; j < 32; j++) acc[j] = 0ULL;
        for (int kk = 0; kk < 16; kk++) {
            float4 anb = __ldg(nb4 + kk);
            float4 ah = __ldg(h4 + kk);
            float an[4] = {anb.x, anb.y, anb.z, anb.w};
            float av[4] = {ah.x, ah.y, ah.z, ah.w};
#pragma unroll
            for (int s = 0; s < 4; s++) {
                int k = kk * 4 + s;
                u64 pa = pack2s(an[s]);
                u64 ph = pack2s(av[s]);
#pragma unroll
                for (int jj = 0; jj < 16; jj++) {
                    ulonglong2 wl = sWl[k * 16 + jj];
                    ulonglong2 wr = sWr[k * 16 + jj];
                    ffma2(acc[2 * jj], pa, wl.x);
                    ffma2(acc[2 * jj], ph, wr.x);
                    ffma2(acc[2 * jj + 1], pa, wl.y);
                    ffma2(acc[2 * jj + 1], ph, wr.y);
                }
            }
        }
        if (valid) {
            float4* o = reinterpret_cast<float4*>(g_h2 + n * D);
#pragma unroll
            for (int jj = 0; jj < 16; jj++) {
                float2 p0 = unpack2(acc[2 * jj]);
                float2 p1 = unpack2(acc[2 * jj + 1]);
                o[jj] = make_float4(fmaxf(p0.x, 0.f), fmaxf(p0.y, 0.f),
                                    fmaxf(p1.x, 0.f), fmaxf(p1.y, 0.f));
            }
        }
    }
}

// ---------------- GIN GEMM: h3 = relu(relu(z@W1+b1)@W2+b2) ----------------
// t staged through g_nb (scratch); same-lane write->read, no sync needed.
__global__ void __launch_bounds__(256) k_gin(const float* __restrict__ W1,
                                             const float* __restrict__ b1,
                                             const float* __restrict__ W2,
                                             const float* __restrict__ b2, int n_nodes) {
    __shared__ ulonglong2 sW1[D * 16];
    __shared__ ulonglong2 sW2[D * 16];
    {
        const ulonglong2* w12 = reinterpret_cast<const ulonglong2*>(W1);
        const ulonglong2* w22 = reinterpret_cast<const ulonglong2*>(W2);
        for (int i = threadIdx.x; i < D * 16; i += blockDim.x) { sW1[i] = w12[i]; sW2[i] = w22[i]; }
    }
    __syncthreads();
    int lane = threadIdx.x & 31, warp = threadIdx.x >> 5;
    int ntiles = (n_nodes + 31) / 32;
    int nwarps = gridDim.x * 8;
    const float4* b1v = reinterpret_cast<const float4*>(b1);
    const float4* b2v = reinterpret_cast<const float4*>(b2);
    for (int tile = blockIdx.x * 8 + warp; tile < ntiles; tile += nwarps) {
        int n = tile * 32 + lane;
        bool valid = n < n_nodes;
        int nn = valid ? n : (n_nodes - 1);
        // ---- layer 1: t = relu(z @ W1 + b1)
        const float4* z4 = reinterpret_cast<const float4*>(g_z + nn * D);
        u64 acc[32];
#pragma unroll
        for (int jj = 0; jj < 16; jj++) {
            float4 bb = __ldg(b1v + jj);
            acc[2 * jj] = pack2(bb.x, bb.y);
            acc[2 * jj + 1] = pack2(bb.z, bb.w);
        }
        for (int kk = 0; kk < 16; kk++) {
            float4 az = __ldg(z4 + kk);
            float av[4] = {az.x, az.y, az.z, az.w};
#pragma unroll
            for (int s = 0; s < 4; s++) {
                int k = kk * 4 + s;
                u64 pz = pack2s(av[s]);
#pragma unroll
                for (int jj = 0; jj < 16; jj++) {
                    ulonglong2 w = sW1[k * 16 + jj];
                    ffma2(acc[2 * jj], pz, w.x);
                    ffma2(acc[2 * jj + 1], pz, w.y);
                }
            }
        }
        // stage t = relu(acc) to g_nb scratch (own row)
        {
            float4* tstage = reinterpret_cast<float4*>(g_nb + nn * D);
#pragma unroll
            for (int jj = 0; jj < 16; jj++) {
                float2 p0 = unpack2(acc[2 * jj]);
                float2 p1 = unpack2(acc[2 * jj + 1]);
                tstage[jj] = make_float4(fmaxf(p0.x, 0.f), fmaxf(p0.y, 0.f),
                                         fmaxf(p1.x, 0.f), fmaxf(p1.y, 0.f));
            }
        }
        // ---- layer 2: h3 = relu(t @ W2 + b2)
#pragma unroll
        for (int jj = 0; jj < 16; jj++) {
            float4 bb = __ldg(b2v + jj);
            acc[2 * jj] = pack2(bb.x, bb.y);
            acc[2 * jj + 1] = pack2(bb.z, bb.w);
        }
        const float4* t4 = reinterpret_cast<const float4*>(g_nb + nn * D);  // plain load (coherent)
        for (int kk = 0; kk < 16; kk++) {
            float4 at = t4[kk];
            float av[4] = {at.x, at.y, at.z, at.w};
#pragma unroll
            for (int s = 0; s < 4; s++) {
                int k = kk * 4 + s;
                u64 pt = pack2s(av[s]);
#pragma unroll
                for (int jj = 0; jj < 16; jj++) {
                    ulonglong2 w = sW2[k * 16 + jj];
                    ffma2(acc[2 * jj], pt, w.x);
                    ffma2(acc[2 * jj + 1], pt, w.y);
                }
            }
        }
        if (valid) {
            float4* o = reinterpret_cast<float4*>(g_h3 + n * D);
#pragma unroll
            for (int jj = 0; jj < 16; jj++) {
                float2 p0 = unpack2(acc[2 * jj]);
                float2 p1 = unpack2(acc[2 * jj + 1]);
                o[jj] = make_float4(fmaxf(p0.x, 0.f), fmaxf(p0.y, 0.f),
                                    fmaxf(p1.x, 0.f), fmaxf(p1.y, 0.f));
            }
        }
    }
}

// ---------------- pooling: batch sorted -> run flushing ----------------
#define POOL_CHUNK 64
__global__ void k_pool(const int* __restrict__ batch, int n_nodes) {
    int j = threadIdx.x;  // 0..63
    int n0 = blockIdx.x * POOL_CHUNK;
    int nend = n0 + POOL_CHUNK;
    if (nend > n_nodes) nend = n_nodes;
    int g = -1;
    float s1 = 0.f, s2 = 0.f, s3 = 0.f, c = 0.f;
    for (int n = n0; n < nend; n++) {
        int bg = batch[n];
        if (bg != g) {
            if (g >= 0) {
                atomicAdd(&g_ps1[g * D + j], s1);
                atomicAdd(&g_ps2[g * D + j], s2);
                atomicAdd(&g_ps3[g * D + j], s3);
                if (j == 0) atomicAdd(&g_cnt[g], c);
            }
            g = bg; s1 = s2 = s3 = 0.f; c = 0.f;
        }
        s1 += g_h1[n * D + j];
        s2 += g_h2[n * D + j];
        s3 += g_h3[n * D + j];
        c += 1.0f;
    }
    if (g >= 0) {
        atomicAdd(&g_ps1[g * D + j], s1);
        atomicAdd(&g_ps2[g * D + j], s2);
        atomicAdd(&g_ps3[g * D + j], s3);
        if (j == 0) atomicAdd(&g_cnt[g], c);
    }
}

// ---------------- final ----------------
__global__ void k_final(const float* __restrict__ Wp1, const float* __restrict__ Wp2,
                        const float* __restrict__ Wp3, float* __restrict__ out, int Gn) {
    __shared__ float s1[D * D];
    __shared__ float s2[D * D];
    __shared__ float s3[D * D];
    for (int i = threadIdx.x; i < D * D; i += blockDim.x) { s1[i] = Wp1[i]; s2[i] = Wp2[i]; s3[i] = Wp3[i]; }
    __syncthreads();
    int warp = threadIdx.x >> 5, lane = threadIdx.x & 31;
    int g = blockIdx.x * 8 + warp;
    if (g >= Gn) return;
    float ic = 1.0f / fmaxf(g_cnt[g], 1.0f);
    float a0 = g_ps1[g * D + lane] * ic, a1 = g_ps1[g * D + lane + 32] * ic;
    float b0 = g_ps2[g * D + lane] * ic, b1 = g_ps2[g * D + lane + 32] * ic;
    float c0 = g_ps3[g * D + lane] * ic, c1 = g_ps3[g * D + lane + 32] * ic;
    float acc0 = 0.f, acc1 = 0.f;
#pragma unroll
    for (int k = 0; k < 32; k++) {
        float va = __shfl_sync(0xffffffffu, a0, k);
        float vb = __shfl_sync(0xffffffffu, b0, k);
        float vc = __shfl_sync(0xffffffffu, c0, k);
        acc0 += va * s1[k * D + lane] + vb * s2[k * D + lane] + vc * s3[k * D + lane];
        acc1 += va * s1[k * D + lane + 32] + vb * s2[k * D + lane + 32] + vc * s3[k * D + lane + 32];
    }
#pragma unroll
    for (int k = 0; k < 32; k++) {
        float va = __shfl_sync(0xffffffffu, a1, k);
        float vb = __shfl_sync(0xffffffffu, b1, k);
        float vc = __shfl_sync(0xffffffffu, c1, k);
        acc0 += va * s1[(k + 32) * D + lane] + vb * s2[(k + 32) * D + lane] + vc * s3[(k + 32) * D + lane];
        acc1 += va * s1[(k + 32) * D + lane + 32] + vb * s2[(k + 32) * D + lane + 32] + vc * s3[(k + 32) * D + lane + 32];
    }
    out[g * D + lane] = fmaxf(acc0, 0.f);
    out[g * D + lane + 32] = fmaxf(acc1, 0.f);
}

// ---------------- launch ----------------
extern "C" void kernel_launch(void* const* d_in, const int* in_sizes, int n_in,
                              void* d_out, int out_size) {
    const int* x      = (const int*)d_in[0];
    const int* ei     = (const int*)d_in[1];
    const int* batch  = (const int*)d_in[2];
    const float* emb  = (const float*)d_in[3];
    const float* Wgcn = (const float*)d_in[4];
    const float* Wsl  = (const float*)d_in[5];
    const float* Wsr  = (const float*)d_in[6];
    const float* Wg1  = (const float*)d_in[7];
    const float* bg1  = (const float*)d_in[8];
    const float* Wg2  = (const float*)d_in[9];
    const float* bg2  = (const float*)d_in[10];
    const float* Wp1  = (const float*)d_in[11];
    const float* Wp2  = (const float*)d_in[12];
    const float* Wp3  = (const float*)d_in[13];
    float* out = (float*)d_out;

    int n = in_sizes[0];
    int e = in_sizes[1] / 2;
    int v = in_sizes[3] / D;
    int g = out_size / D;

    k_init<<<256, 256>>>(emb, Wgcn, v, n);
    k_hist<<<(e + 255) / 256, 256>>>(ei, e);
    k_scan<<<1, 1024>>>(n);
    k_scatter<<<(e + 255) / 256, 256>>>(ei, e);

    int gth = n * 16;
    int gblk = (gth + 255) / 256;
    k_gather_gcn<<<gblk, 256>>>(x, n);
    k_gather_mean<<<gblk, 256>>>(n);

    int ntiles = (n + 31) / 32;
    int ggrid = (ntiles + 7) / 8;
    k_sage<<<ggrid, 256>>>(Wsl, Wsr, n);
    k_gather_gin<<<gblk, 256>>>(n);
    k_gin<<<ggrid, 256>>>(Wg1, bg1, Wg2, bg2, n);
    k_pool<<<(n + POOL_CHUNK - 1) / POOL_CHUNK, D>>>(batch, n);
    k_final<<<(g + 7) / 8, 256>>>(Wp1, Wp2, Wp3, out, g);
}

// round 6
// speedup vs baseline: 1.5354x; 1.1030x over previous
#include <cuda_runtime.h>

#define D 64
#define MAXN 50000
#define MAXE 800000
#define MAXG 512
#define MAXV 128

typedef unsigned long long u64;

// ---------------- scratch (device globals; no allocation) ----------------
__device__ __align__(128) float g_embW[MAXV * D];
__device__ __align__(128) float g_h1[MAXN * D];
__device__ __align__(128) float g_nb[MAXN * D];   // SAGE mean; later GIN t-stage scratch
__device__ __align__(128) float g_h2[MAXN * D];
__device__ __align__(128) float g_z[MAXN * D];
__device__ __align__(128) float g_h3[MAXN * D];
__device__ __align__(128) float g_ps1[MAXG * D];
__device__ __align__(128) float g_ps2[MAXG * D];
__device__ __align__(128) float g_ps3[MAXG * D];
__device__ __align__(128) float g_cnt[MAXG];
// CSR build
__device__ __align__(128) int g_deg[MAXN];          // zeroed by k_scan after use
__device__ __align__(128) int g_off[MAXN + 4];
__device__ __align__(128) int g_cursor[MAXN];
__device__ __align__(128) int g_srcs[MAXE];
__device__ __align__(128) int g_xs[MAXE];           // x[src] per CSR slot

__device__ __forceinline__ float4 f4add(float4 a, float4 b) {
    return make_float4(a.x + b.x, a.y + b.y, a.z + b.z, a.w + b.w);
}

// packed f32x2 helpers (Blackwell)
__device__ __forceinline__ u64 pack2s(float x) {
    u64 r; asm("mov.b64 %0, {%1,%1};" : "=l"(r) : "f"(x)); return r;
}
__device__ __forceinline__ u64 pack2(float x, float y) {
    u64 r; asm("mov.b64 %0, {%1,%2};" : "=l"(r) : "f"(x), "f"(y)); return r;
}
__device__ __forceinline__ void ffma2(u64& d, u64 a, u64 b) {
    asm("fma.rn.f32x2 %0, %1, %2, %3;" : "=l"(d) : "l"(a), "l"(b), "l"(d));
}
__device__ __forceinline__ float2 unpack2(u64 v) {
    float2 f; asm("mov.b64 {%0,%1}, %2;" : "=f"(f.x), "=f"(f.y) : "l"(v)); return f;
}

// ---------------- pre: embW = emb@W + degree histogram ----------------
__global__ void k_pre(const int* __restrict__ ei, const float* __restrict__ emb,
                      const float* __restrict__ W, int Vn, int E_) {
    int gid = blockIdx.x * blockDim.x + threadIdx.x;
    int stride = gridDim.x * blockDim.x;
    for (int idx = gid; idx < Vn * D; idx += stride) {
        int v = idx >> 6, j = idx & 63;
        float s = 0.f;
#pragma unroll
        for (int k = 0; k < D; k++) s += emb[v * D + k] * W[k * D + j];
        g_embW[idx] = s;
    }
    // histogram: 4 independent edges per thread per iter
    for (int base = gid * 4; base < E_; base += stride * 4) {
#pragma unroll
        for (int u = 0; u < 4; u++) {
            int e = base + u;
            if (e < E_) atomicAdd(&g_deg[__ldg(&ei[E_ + e])], 1);
        }
    }
}

// ---------------- single-block exclusive scan (int4, 4096 elems/iter) ----------------
// off/cursor = exclusive prefix of deg; off[n]=E sentinel; zeroes deg after use.
__global__ void __launch_bounds__(1024) k_scan(int n) {
    __shared__ int wsum[32];
    __shared__ int s_total;
    int tid = threadIdx.x, lane = tid & 31, warp = tid >> 5;
    int carry = 0;
    for (int base = 0; base < n; base += 4096) {
        int i4 = base + tid * 4;
        int4 v = make_int4(0, 0, 0, 0);
        if (i4 + 3 < n) {
            v = *reinterpret_cast<const int4*>(g_deg + i4);
        } else if (i4 < n) {
            v.x = g_deg[i4];
            if (i4 + 1 < n) v.y = g_deg[i4 + 1];
            if (i4 + 2 < n) v.z = g_deg[i4 + 2];
        }
        int sum = v.x + v.y + v.z + v.w;
        int inc = sum;
#pragma unroll
        for (int off = 1; off < 32; off <<= 1) {
            int tv = __shfl_up_sync(0xffffffffu, inc, off);
            if (lane >= off) inc += tv;
        }
        if (lane == 31) wsum[warp] = inc;
        __syncthreads();
        if (warp == 0) {
            int w = wsum[lane];
            int wi = w;
#pragma unroll
            for (int off = 1; off < 32; off <<= 1) {
                int tv = __shfl_up_sync(0xffffffffu, wi, off);
                if (lane >= off) wi += tv;
            }
            wsum[lane] = wi - w;           // exclusive warp offset
            if (lane == 31) s_total = wi;  // block total this tile
        }
        __syncthreads();
        int b0 = carry + inc - sum + wsum[warp];
        int4 o;
        o.x = b0;
        o.y = b0 + v.x;
        o.z = b0 + v.x + v.y;
        o.w = b0 + v.x + v.y + v.z;
        if (i4 + 3 < n) {
            *reinterpret_cast<int4*>(g_off + i4) = o;
            *reinterpret_cast<int4*>(g_cursor + i4) = o;
            *reinterpret_cast<int4*>(g_deg + i4) = make_int4(0, 0, 0, 0);
        } else if (i4 < n) {
            int ov[4] = {o.x, o.y, o.z, o.w};
#pragma unroll
            for (int u = 0; u < 4; u++) {
                if (i4 + u < n) { g_off[i4 + u] = ov[u]; g_cursor[i4 + u] = ov[u]; g_deg[i4 + u] = 0; }
            }
        }
        carry += s_total;
        __syncthreads();
    }
    if (tid == 0) g_off[n] = carry;  // sentinel = E
}

// ---------------- scatter: fill CSR src + x[src] arrays (4 edges/thread) ----------------
__global__ void k_scatter(const int* __restrict__ ei, const int* __restrict__ x, int E_) {
    int e0 = (blockIdx.x * blockDim.x + threadIdx.x) * 4;
#pragma unroll
    for (int u = 0; u < 4; u++) {
        int e = e0 + u;
        if (e < E_) {
            int src = __ldg(&ei[e]);
            int dst = __ldg(&ei[E_ + e]);
            int xv = __ldg(&x[src]);
            int pos = atomicAdd(&g_cursor[dst], 1);
            g_srcs[pos] = src;
            g_xs[pos] = xv;
        }
    }
}

// ---------------- GCN gather: h1[n] = relu(sum_nb embW[xs]) ----------------
__global__ void k_gather_gcn(int n_nodes) {
    int gid = blockIdx.x * blockDim.x + threadIdx.x;
    int node = gid >> 4, q = gid & 15;
    if (node >= n_nodes) return;
    int start = g_off[node];
    int cnt = g_off[node + 1] - start;
    const float4* embW4 = reinterpret_cast<const float4*>(g_embW);
    float4 acc = make_float4(0.f, 0.f, 0.f, 0.f);
    int t = 0;
    for (; t + 4 <= cnt; t += 4) {
        int r0 = __ldg(&g_xs[start + t]);
        int r1 = __ldg(&g_xs[start + t + 1]);
        int r2 = __ldg(&g_xs[start + t + 2]);
        int r3 = __ldg(&g_xs[start + t + 3]);
        float4 v0 = embW4[r0 * 16 + q];
        float4 v1 = embW4[r1 * 16 + q];
        float4 v2 = embW4[r2 * 16 + q];
        float4 v3 = embW4[r3 * 16 + q];
        acc = f4add(acc, f4add(f4add(v0, v1), f4add(v2, v3)));
    }
    for (; t < cnt; t++) {
        int r = __ldg(&g_xs[start + t]);
        acc = f4add(acc, embW4[r * 16 + q]);
    }
    acc.x = fmaxf(acc.x, 0.f); acc.y = fmaxf(acc.y, 0.f);
    acc.z = fmaxf(acc.z, 0.f); acc.w = fmaxf(acc.w, 0.f);
    reinterpret_cast<float4*>(g_h1 + node * D)[q] = acc;
}

// ---------------- SAGE gather: nb[n] = mean_nb h1[src] ----------------
__global__ void k_gather_mean(int n_nodes) {
    int gid = blockIdx.x * blockDim.x + threadIdx.x;
    int node = gid >> 4, q = gid & 15;
    if (node >= n_nodes) return;
    int start = g_off[node];
    int cnt = g_off[node + 1] - start;
    float4 acc = make_float4(0.f, 0.f, 0.f, 0.f);
    int t = 0;
    for (; t + 4 <= cnt; t += 4) {
        int s0 = __ldg(&g_srcs[start + t]);
        int s1 = __ldg(&g_srcs[start + t + 1]);
        int s2 = __ldg(&g_srcs[start + t + 2]);
        int s3 = __ldg(&g_srcs[start + t + 3]);
        float4 v0 = reinterpret_cast<const float4*>(g_h1 + s0 * D)[q];
        float4 v1 = reinterpret_cast<const float4*>(g_h1 + s1 * D)[q];
        float4 v2 = reinterpret_cast<const float4*>(g_h1 + s2 * D)[q];
        float4 v3 = reinterpret_cast<const float4*>(g_h1 + s3 * D)[q];
        acc = f4add(acc, f4add(f4add(v0, v1), f4add(v2, v3)));
    }
    for (; t < cnt; t++) {
        int s = __ldg(&g_srcs[start + t]);
        acc = f4add(acc, reinterpret_cast<const float4*>(g_h1 + s * D)[q]);
    }
    float invd = 1.0f / fmaxf((float)cnt, 1.0f);
    acc.x *= invd; acc.y *= invd; acc.z *= invd; acc.w *= invd;
    reinterpret_cast<float4*>(g_nb + node * D)[q] = acc;
}

// ---------------- GIN gather: z[n] = h2[n] + sum_nb h2[src] ----------------
__global__ void k_gather_gin(int n_nodes) {
    int gid = blockIdx.x * blockDim.x + threadIdx.x;
    int node = gid >> 4, q = gid & 15;
    if (node >= n_nodes) return;
    int start = g_off[node];
    int cnt = g_off[node + 1] - start;
    float4 acc = reinterpret_cast<const float4*>(g_h2 + node * D)[q];
    int t = 0;
    for (; t + 4 <= cnt; t += 4) {
        int s0 = __ldg(&g_srcs[start + t]);
        int s1 = __ldg(&g_srcs[start + t + 1]);
        int s2 = __ldg(&g_srcs[start + t + 2]);
        int s3 = __ldg(&g_srcs[start + t + 3]);
        float4 v0 = reinterpret_cast<const float4*>(g_h2 + s0 * D)[q];
        float4 v1 = reinterpret_cast<const float4*>(g_h2 + s1 * D)[q];
        float4 v2 = reinterpret_cast<const float4*>(g_h2 + s2 * D)[q];
        float4 v3 = reinterpret_cast<const float4*>(g_h2 + s3 * D)[q];
        acc = f4add(acc, f4add(f4add(v0, v1), f4add(v2, v3)));
    }
    for (; t < cnt; t++) {
        int s = __ldg(&g_srcs[start + t]);
        acc = f4add(acc, reinterpret_cast<const float4*>(g_h2 + s * D)[q]);
    }
    reinterpret_cast<float4*>(g_z + node * D)[q] = acc;
}

// ---------------- SAGE GEMM: h2 = relu(nb @ Wl + h1 @ Wr) ----------------
__global__ void __launch_bounds__(256) k_sage(const float* __restrict__ Wl,
                                              const float* __restrict__ Wr, int n_nodes) {
    __shared__ ulonglong2 sWl[D * 16];
    __shared__ ulonglong2 sWr[D * 16];
    {
        const ulonglong2* wl2 = reinterpret_cast<const ulonglong2*>(Wl);
        const ulonglong2* wr2 = reinterpret_cast<const ulonglong2*>(Wr);
        for (int i = threadIdx.x; i < D * 16; i += blockDim.x) { sWl[i] = wl2[i]; sWr[i] = wr2[i]; }
    }
    __syncthreads();
    int lane = threadIdx.x & 31, warp = threadIdx.x >> 5;
    int ntiles = (n_nodes + 31) / 32;
    int nwarps = gridDim.x * 8;
    for (int tile = blockIdx.x * 8 + warp; tile < ntiles; tile += nwarps) {
        int n = tile * 32 + lane;
        bool valid = n < n_nodes;
        int nn = valid ? n : (n_nodes - 1);
        const float4* nb4 = reinterpret_cast<const float4*>(g_nb + nn * D);
        const float4* h4 = reinterpret_cast<const float4*>(g_h1 + nn * D);
        u64 acc[32];
#pragma unroll
        for (int j = 0; j < 32; j++) acc[j] = 0ULL;
        for (int kk = 0; kk < 16; kk++) {
            float4 anb = __ldg(nb4 + kk);
            float4 ah = __ldg(h4 + kk);
            float an[4] = {anb.x, anb.y, anb.z, anb.w};
            float av[4] = {ah.x, ah.y, ah.z, ah.w};
#pragma unroll
            for (int s = 0; s < 4; s++) {
                int k = kk * 4 + s;
                u64 pa = pack2s(an[s]);
                u64 ph = pack2s(av[s]);
#pragma unroll
                for (int jj = 0; jj < 16; jj++) {
                    ulonglong2 wl = sWl[k * 16 + jj];
                    ulonglong2 wr = sWr[k * 16 + jj];
                    ffma2(acc[2 * jj], pa, wl.x);
                    ffma2(acc[2 * jj], ph, wr.x);
                    ffma2(acc[2 * jj + 1], pa, wl.y);
                    ffma2(acc[2 * jj + 1], ph, wr.y);
                }
            }
        }
        if (valid) {
            float4* o = reinterpret_cast<float4*>(g_h2 + n * D);
#pragma unroll
            for (int jj = 0; jj < 16; jj++) {
                float2 p0 = unpack2(acc[2 * jj]);
                float2 p1 = unpack2(acc[2 * jj + 1]);
                o[jj] = make_float4(fmaxf(p0.x, 0.f), fmaxf(p0.y, 0.f),
                                    fmaxf(p1.x, 0.f), fmaxf(p1.y, 0.f));
            }
        }
    }
}

// ---------------- GIN GEMM: h3 = relu(relu(z@W1+b1)@W2+b2) ----------------
__global__ void __launch_bounds__(256) k_gin(const float* __restrict__ W1,
                                             const float* __restrict__ b1,
                                             const float* __restrict__ W2,
                                             const float* __restrict__ b2, int n_nodes) {
    __shared__ ulonglong2 sW1[D * 16];
    __shared__ ulonglong2 sW2[D * 16];
    {
        const ulonglong2* w12 = reinterpret_cast<const ulonglong2*>(W1);
        const ulonglong2* w22 = reinterpret_cast<const ulonglong2*>(W2);
        for (int i = threadIdx.x; i < D * 16; i += blockDim.x) { sW1[i] = w12[i]; sW2[i] = w22[i]; }
    }
    __syncthreads();
    int lane = threadIdx.x & 31, warp = threadIdx.x >> 5;
    int ntiles = (n_nodes + 31) / 32;
    int nwarps = gridDim.x * 8;
    const float4* b1v = reinterpret_cast<const float4*>(b1);
    const float4* b2v = reinterpret_cast<const float4*>(b2);
    for (int tile = blockIdx.x * 8 + warp; tile < ntiles; tile += nwarps) {
        int n = tile * 32 + lane;
        bool valid = n < n_nodes;
        int nn = valid ? n : (n_nodes - 1);
        const float4* z4 = reinterpret_cast<const float4*>(g_z + nn * D);
        u64 acc[32];
#pragma unroll
        for (int jj = 0; jj < 16; jj++) {
            float4 bb = __ldg(b1v + jj);
            acc[2 * jj] = pack2(bb.x, bb.y);
            acc[2 * jj + 1] = pack2(bb.z, bb.w);
        }
        for (int kk = 0; kk < 16; kk++) {
            float4 az = __ldg(z4 + kk);
            float av[4] = {az.x, az.y, az.z, az.w};
#pragma unroll
            for (int s = 0; s < 4; s++) {
                int k = kk * 4 + s;
                u64 pz = pack2s(av[s]);
#pragma unroll
                for (int jj = 0; jj < 16; jj++) {
                    ulonglong2 w = sW1[k * 16 + jj];
                    ffma2(acc[2 * jj], pz, w.x);
                    ffma2(acc[2 * jj + 1], pz, w.y);
                }
            }
        }
        {
            float4* tstage = reinterpret_cast<float4*>(g_nb + nn * D);
#pragma unroll
            for (int jj = 0; jj < 16; jj++) {
                float2 p0 = unpack2(acc[2 * jj]);
                float2 p1 = unpack2(acc[2 * jj + 1]);
                tstage[jj] = make_float4(fmaxf(p0.x, 0.f), fmaxf(p0.y, 0.f),
                                         fmaxf(p1.x, 0.f), fmaxf(p1.y, 0.f));
            }
        }
#pragma unroll
        for (int jj = 0; jj < 16; jj++) {
            float4 bb = __ldg(b2v + jj);
            acc[2 * jj] = pack2(bb.x, bb.y);
            acc[2 * jj + 1] = pack2(bb.z, bb.w);
        }
        const float4* t4 = reinterpret_cast<const float4*>(g_nb + nn * D);
        for (int kk = 0; kk < 16; kk++) {
            float4 at = t4[kk];
            float av[4] = {at.x, at.y, at.z, at.w};
#pragma unroll
            for (int s = 0; s < 4; s++) {
                int k = kk * 4 + s;
                u64 pt = pack2s(av[s]);
#pragma unroll
                for (int jj = 0; jj < 16; jj++) {
                    ulonglong2 w = sW2[k * 16 + jj];
                    ffma2(acc[2 * jj], pt, w.x);
                    ffma2(acc[2 * jj + 1], pt, w.y);
                }
            }
        }
        if (valid) {
            float4* o = reinterpret_cast<float4*>(g_h3 + n * D);
#pragma unroll
            for (int jj = 0; jj < 16; jj++) {
                float2 p0 = unpack2(acc[2 * jj]);
                float2 p1 = unpack2(acc[2 * jj + 1]);
                o[jj] = make_float4(fmaxf(p0.x, 0.f), fmaxf(p0.y, 0.f),
                                    fmaxf(p1.x, 0.f), fmaxf(p1.y, 0.f));
            }
        }
    }
}

// ---------------- pooling: batch sorted -> run flushing (ps zeroed by k_final) ----
#define POOL_CHUNK 64
__global__ void k_pool(const int* __restrict__ batch, int n_nodes) {
    int j = threadIdx.x;  // 0..63
    int n0 = blockIdx.x * POOL_CHUNK;
    int nend = n0 + POOL_CHUNK;
    if (nend > n_nodes) nend = n_nodes;
    int g = -1;
    float s1 = 0.f, s2 = 0.f, s3 = 0.f, c = 0.f;
    for (int n = n0; n < nend; n++) {
        int bg = batch[n];
        if (bg != g) {
            if (g >= 0) {
                atomicAdd(&g_ps1[g * D + j], s1);
                atomicAdd(&g_ps2[g * D + j], s2);
                atomicAdd(&g_ps3[g * D + j], s3);
                if (j == 0) atomicAdd(&g_cnt[g], c);
            }
            g = bg; s1 = s2 = s3 = 0.f; c = 0.f;
        }
        s1 += g_h1[n * D + j];
        s2 += g_h2[n * D + j];
        s3 += g_h3[n * D + j];
        c += 1.0f;
    }
    if (g >= 0) {
        atomicAdd(&g_ps1[g * D + j], s1);
        atomicAdd(&g_ps2[g * D + j], s2);
        atomicAdd(&g_ps3[g * D + j], s3);
        if (j == 0) atomicAdd(&g_cnt[g], c);
    }
}

// ---------------- final: consume pooled sums, then zero them for next call ------
__global__ void k_final(const float* __restrict__ Wp1, const float* __restrict__ Wp2,
                        const float* __restrict__ Wp3, float* __restrict__ out, int Gn) {
    __shared__ float s1[D * D];
    __shared__ float s2[D * D];
    __shared__ float s3[D * D];
    for (int i = threadIdx.x; i < D * D; i += blockDim.x) { s1[i] = Wp1[i]; s2[i] = Wp2[i]; s3[i] = Wp3[i]; }
    __syncthreads();
    int warp = threadIdx.x >> 5, lane = threadIdx.x & 31;
    int g = blockIdx.x * 8 + warp;
    if (g >= Gn) return;
    float cv = g_cnt[g];
    float ic = 1.0f / fmaxf(cv, 1.0f);
    float a0 = g_ps1[g * D + lane] * ic, a1 = g_ps1[g * D + lane + 32] * ic;
    float b0 = g_ps2[g * D + lane] * ic, b1 = g_ps2[g * D + lane + 32] * ic;
    float c0 = g_ps3[g * D + lane] * ic, c1 = g_ps3[g * D + lane + 32] * ic;
    // restore zero-state for next call
    g_ps1[g * D + lane] = 0.f; g_ps1[g * D + lane + 32] = 0.f;
    g_ps2[g * D + lane] = 0.f; g_ps2[g * D + lane + 32] = 0.f;
    g_ps3[g * D + lane] = 0.f; g_ps3[g * D + lane + 32] = 0.f;
    if (lane == 0) g_cnt[g] = 0.f;
    float acc0 = 0.f, acc1 = 0.f;
#pragma unroll
    for (int k = 0; k < 32; k++) {
        float va = __shfl_sync(0xffffffffu, a0, k);
        float vb = __shfl_sync(0xffffffffu, b0, k);
        float vc = __shfl_sync(0xffffffffu, c0, k);
        acc0 += va * s1[k * D + lane] + vb * s2[k * D + lane] + vc * s3[k * D + lane];
        acc1 += va * s1[k * D + lane + 32] + vb * s2[k * D + lane + 32] + vc * s3[k * D + lane + 32];
    }
#pragma unroll
    for (int k = 0; k < 32; k++) {
        float va = __shfl_sync(0xffffffffu, a1, k);
        float vb = __shfl_sync(0xffffffffu, b1, k);
        float vc = __shfl_sync(0xffffffffu, c1, k);
        acc0 += va * s1[(k + 32) * D + lane] + vb * s2[(k + 32) * D + lane] + vc * s3[(k + 32) * D + lane];
        acc1 += va * s1[(k + 32) * D + lane + 32] + vb * s2[(k + 32) * D + lane + 32] + vc * s3[(k + 32) * D + lane + 32];
    }
    out[g * D + lane] = fmaxf(acc0, 0.f);
    out[g * D + lane + 32] = fmaxf(acc1, 0.f);
}

// ---------------- launch ----------------
extern "C" void kernel_launch(void* const* d_in, const int* in_sizes, int n_in,
                              void* d_out, int out_size) {
    const int* x      = (const int*)d_in[0];
    const int* ei     = (const int*)d_in[1];
    const int* batch  = (const int*)d_in[2];
    const float* emb  = (const float*)d_in[3];
    const float* Wgcn = (const float*)d_in[4];
    const float* Wsl  = (const float*)d_in[5];
    const float* Wsr  = (const float*)d_in[6];
    const float* Wg1  = (const float*)d_in[7];
    const float* bg1  = (const float*)d_in[8];
    const float* Wg2  = (const float*)d_in[9];
    const float* bg2  = (const float*)d_in[10];
    const float* Wp1  = (const float*)d_in[11];
    const float* Wp2  = (const float*)d_in[12];
    const float* Wp3  = (const float*)d_in[13];
    float* out = (float*)d_out;

    int n = in_sizes[0];
    int e = in_sizes[1] / 2;
    int v = in_sizes[3] / D;
    int g = out_size / D;

    int preblk = (e / 4 + 255) / 256;
    k_pre<<<preblk, 256>>>(ei, emb, Wgcn, v, e);
    k_scan<<<1, 1024>>>(n);
    k_scatter<<<(e / 4 + 255) / 256, 256>>>(ei, x, e);

    int gth = n * 16;
    int gblk = (gth + 255) / 256;
    k_gather_gcn<<<gblk, 256>>>(n);
    k_gather_mean<<<gblk, 256>>>(n);

    int ntiles = (n + 31) / 32;
    int ggrid = (ntiles + 7) / 8;
    k_sage<<<ggrid, 256>>>(Wsl, Wsr, n);
    k_gather_gin<<<gblk, 256>>>(n);
    k_gin<<<ggrid, 256>>>(Wg1, bg1, Wg2, bg2, n);
    k_pool<<<(n + POOL_CHUNK - 1) / POOL_CHUNK, D>>>(batch, n);
    k_final<<<(g + 7) / 8, 256>>>(Wp1, Wp2, Wp3, out, g);
}